// round 16
// baseline (speedup 1.0000x reference)
#include <cuda_runtime.h>
#include <cstdint>

#define BS 32
#define NANCH 90000
#define NVEC (NANCH / 4)       // 22500 float4 per batch
#define NQ 4                   // slices per batch (grid 128 <= 148 SMs: ONE wave)
#define QVEC (NVEC / NQ)       // 5625
#define KPRE 1000
#define KPOST 300
#define NWORDS 16              // 16*64 = 1024 >= 1000
#define NMS_THR 0.7f

#define HBITS 12
#define NBINS (1 << HBITS)     // 4096
#define HSHIFT (32 - HBITS)    // 20
#define BPT (NBINS / 1024)     // 4 bins per thread
#define QCAP 4096
#define CANDCAP 4096
// bin of logit 2.0f: flip_f(2.0f) = 0xC0000000, >>20 = 0xC00 = 3072.
// Speculative gather threshold. P(logit>2.0)~0.0228 -> ~2052 cands/batch.
// Exactness guarded: if gathered >= KPRE with no overflow, bin ordering
// implies top-1000 is a subset of the gathered set. Else exact fallback.
#define GUESS_BIN 3072u

typedef unsigned long long u64;

// ---------------- scratch (static device globals; no allocation) ----------------
__device__ unsigned g_qcnt[BS][NQ];                    // RAW counts (overflow check)
__device__ u64      g_qcand[BS][NQ][QCAP];
__device__ unsigned g_sync[BS];                        // K1 election counters
__device__ float4   g_boxes[BS][KPRE];
__device__ float    g_scores[BS][KPRE];
__device__ __align__(128) u64 g_mask[BS][KPRE][NWORDS]; // lower-tri never written/read

// float -> order-preserving uint (ascending)
__device__ __forceinline__ unsigned flip_f(float f) {
    unsigned u = __float_as_uint(f);
    return (u & 0x80000000u) ? ~u : (u | 0x80000000u);
}
__device__ __forceinline__ float unflip_f(unsigned k) {
    unsigned u = (k & 0x80000000u) ? (k ^ 0x80000000u) : ~k;
    return __uint_as_float(u);
}
__device__ __forceinline__ float read_dim(const int* p) {
    int v = *p;
    if (v > 0 && v < (1 << 24)) return (float)v;
    return __int_as_float(v);
}

// CTA suffix-threshold via warp shfl (FALLBACK PATH ONLY).
__device__ __forceinline__ void find_threshold(
    const unsigned* hist, unsigned* s_wsum, unsigned* s_wafter, unsigned* s_t,
    int tid)
{
    const int lane = tid & 31;
    const int wrp  = tid >> 5;
    const int base = tid * BPT;
    unsigned s = 0;
    #pragma unroll
    for (int k = 0; k < BPT; ++k) s += hist[base + k];

    unsigned val = s;
    #pragma unroll
    for (int off = 1; off < 32; off <<= 1) {
        unsigned v = __shfl_down_sync(0xFFFFFFFFu, val, off);
        if (lane + off < 32) val += v;
    }
    if (lane == 0) s_wsum[wrp] = val;
    __syncthreads();

    if (wrp == 0) {
        unsigned t0 = s_wsum[lane];
        unsigned v0 = t0;
        #pragma unroll
        for (int off = 1; off < 32; off <<= 1) {
            unsigned v = __shfl_down_sync(0xFFFFFFFFu, v0, off);
            if (lane + off < 32) v0 += v;
        }
        s_wafter[lane] = v0 - t0;
    }
    __syncthreads();

    unsigned mine  = val + s_wafter[wrp];
    unsigned above = mine - s;
    if (mine >= KPRE && above < KPRE) {
        unsigned acc = above;
        int t = base;
        #pragma unroll
        for (int k = BPT - 1; k >= 0; --k) {
            acc += hist[base + k];
            if (acc >= KPRE) { t = base + k; break; }
        }
        *s_t = (unsigned)t;
    }
}

// =============================================================================
// K1: histogram-free. Slice phase: pure speculative gather (bin >= GUESS_BIN).
// Elected CTA: verify speculation -> concat lists -> sort -> decode.
// Fallback (never on this data; exact on any data): hist + threshold + gather.
// grid (NQ, BS) = 128 CTAs (one wave), 1024 threads.
// =============================================================================
extern __shared__ unsigned s_dynA[];   // 32 KB: cand u64[CANDCAP] (hist aliased in fallback)

__global__ __launch_bounds__(1024, 2) void select_fused_kernel(
    const float* __restrict__ logits,
    const float* __restrict__ deltas,
    const float* __restrict__ anchors,
    const int* __restrict__ p_ih,
    const int* __restrict__ p_iw)
{
    const int b   = blockIdx.y;
    const int q   = blockIdx.x;
    const int tid = threadIdx.x;

    unsigned* hist = s_dynA;                 // fallback only
    u64*      cand = (u64*)s_dynA;
    __shared__ unsigned s_wsum[32];
    __shared__ unsigned s_wafter[32];
    __shared__ unsigned s_t;
    __shared__ unsigned s_cnt;
    __shared__ int s_last;

    const float4* lg4 = (const float4*)(logits + (size_t)b * NANCH);
    const int v0 = q * QVEC;
    const int v1 = v0 + QVEC;

    if (tid == 0) s_cnt = 0u;
    __syncthreads();

    // ---- single sweep: speculative gather only (no histogram) ----
    for (int i = v0 + tid; i < v1; i += 1024) {
        float4 v = lg4[i];
        unsigned k0 = flip_f(v.x);
        unsigned k1 = flip_f(v.y);
        unsigned k2 = flip_f(v.z);
        unsigned k3 = flip_f(v.w);
        const int i0 = 4 * i;
        if ((k0 >> HSHIFT) >= GUESS_BIN) {
            unsigned p = atomicAdd(&s_cnt, 1u);
            if (p < QCAP) g_qcand[b][q][p] = ((u64)k0 << 32) | (unsigned)(~(unsigned)(i0));
        }
        if ((k1 >> HSHIFT) >= GUESS_BIN) {
            unsigned p = atomicAdd(&s_cnt, 1u);
            if (p < QCAP) g_qcand[b][q][p] = ((u64)k1 << 32) | (unsigned)(~(unsigned)(i0 + 1));
        }
        if ((k2 >> HSHIFT) >= GUESS_BIN) {
            unsigned p = atomicAdd(&s_cnt, 1u);
            if (p < QCAP) g_qcand[b][q][p] = ((u64)k2 << 32) | (unsigned)(~(unsigned)(i0 + 2));
        }
        if ((k3 >> HSHIFT) >= GUESS_BIN) {
            unsigned p = atomicAdd(&s_cnt, 1u);
            if (p < QCAP) g_qcand[b][q][p] = ((u64)k3 << 32) | (unsigned)(~(unsigned)(i0 + 3));
        }
    }
    __syncthreads();

    // ---- publish raw count, elect last CTA of this batch ----
    if (tid == 0) {
        g_qcnt[b][q] = s_cnt;                 // RAW (for overflow detection)
        __threadfence();
        unsigned old = atomicAdd(&g_sync[b], 1u);
        s_last = (old == NQ - 1);
        if (s_last) g_sync[b] = 0u;
    }
    __syncthreads();
    if (!s_last) return;

    // =================== global select (elected CTA only) ===================
    __threadfence();

    const unsigned r0 = g_qcnt[b][0];
    const unsigned r1 = g_qcnt[b][1];
    const unsigned r2 = g_qcnt[b][2];
    const unsigned r3 = g_qcnt[b][3];
    const unsigned total = r0 + r1 + r2 + r3;
    const bool spec_ok = (r0 <= QCAP) && (r1 <= QCAP) && (r2 <= QCAP) && (r3 <= QCAP)
                      && (total >= KPRE) && (total <= CANDCAP);

    int n;
    if (spec_ok) {
        // ---- concat the 4 slice lists (prefix offsets, no atomics) ----
        const unsigned off1 = r0, off2 = r0 + r1, off3 = r0 + r1 + r2;
        for (unsigned i = tid; i < r0; i += 1024) cand[i]        = g_qcand[b][0][i];
        for (unsigned i = tid; i < r1; i += 1024) cand[off1 + i] = g_qcand[b][1][i];
        for (unsigned i = tid; i < r2; i += 1024) cand[off2 + i] = g_qcand[b][2][i];
        for (unsigned i = tid; i < r3; i += 1024) cand[off3 + i] = g_qcand[b][3][i];
        n = (int)total;
    } else {
        // ---- exact fallback: hist -> threshold -> gather (cold path) ----
        for (int i = tid; i < NBINS; i += 1024) hist[i] = 0u;
        if (tid == 0) s_cnt = 0u;
        __syncthreads();
        for (int i = tid; i < NVEC; i += 1024) {
            float4 v = lg4[i];
            atomicAdd(&hist[flip_f(v.x) >> HSHIFT], 1u);
            atomicAdd(&hist[flip_f(v.y) >> HSHIFT], 1u);
            atomicAdd(&hist[flip_f(v.z) >> HSHIFT], 1u);
            atomicAdd(&hist[flip_f(v.w) >> HSHIFT], 1u);
        }
        __syncthreads();
        find_threshold(hist, s_wsum, s_wafter, &s_t, tid);
        __syncthreads();
        const unsigned t = s_t;
        __syncthreads();        // hist reads done before cand overwrites
        for (int i = tid; i < NVEC; i += 1024) {
            float4 v = lg4[i];
            unsigned kk[4] = { flip_f(v.x), flip_f(v.y), flip_f(v.z), flip_f(v.w) };
            const int i0 = 4 * i;
            #pragma unroll
            for (int c = 0; c < 4; ++c) {
                if ((kk[c] >> HSHIFT) >= t) {
                    unsigned p = atomicAdd(&s_cnt, 1u);
                    if (p < CANDCAP)
                        cand[p] = ((u64)kk[c] << 32) | (unsigned)(~(unsigned)(i0 + c));
                }
            }
        }
        __syncthreads();
        n = min((int)s_cnt, CANDCAP);
    }
    __syncthreads();

    const int S = (n <= 2048) ? 2048 : CANDCAP;
    for (int i = n + tid; i < S; i += 1024) cand[i] = 0ull;

    // ---- bitonic sort desc; full barrier only around cross-warp strides ----
    int prev_big = 1;
    for (int size = 2; size <= S; size <<= 1) {
        for (int stride = size >> 1; stride > 0; stride >>= 1) {
            const int big = (stride >= 32);
            if (big || prev_big) __syncthreads(); else __syncwarp();
            for (int k = tid; k < (S >> 1); k += 1024) {
                int i = 2 * k - (k & (stride - 1));
                int j = i + stride;
                u64 a = cand[i];
                u64 c = cand[j];
                bool desc = ((i & size) == 0);
                if ((a < c) == desc) { cand[i] = c; cand[j] = a; }
            }
            prev_big = big;
        }
    }
    __syncthreads();

    // ---- decode + clip top-1000 ----
    const float fw = read_dim(p_iw);
    const float fh = read_dim(p_ih);
    if (tid < KPRE) {
        u64 comp = cand[tid];
        unsigned idx = ~(unsigned)(comp & 0xFFFFFFFFull);
        unsigned key = (unsigned)(comp >> 32);
        float logit = unflip_f(key);
        float score = 1.0f / (1.0f + expf(-logit));

        float4 d = ((const float4*)deltas)[(size_t)b * NANCH + idx];
        float4 a = ((const float4*)anchors)[idx];
        float aw  = a.z - a.x;
        float ah  = a.w - a.y;
        float acx = a.x + 0.5f * aw;
        float acy = a.y + 0.5f * ah;
        float cx = d.x * aw + acx;
        float cy = d.y * ah + acy;
        float w  = expf(d.z) * aw;
        float h  = expf(d.w) * ah;
        float x1 = fminf(fmaxf(cx - 0.5f * w, 0.0f), fw);
        float y1 = fminf(fmaxf(cy - 0.5f * h, 0.0f), fh);
        float x2 = fminf(fmaxf(cx + 0.5f * w, 0.0f), fw);
        float y2 = fminf(fmaxf(cy + 0.5f * h, 0.0f), fh);
        g_boxes[b][tid]  = make_float4(x1, y1, x2, y2);
        g_scores[b][tid] = score;
    }
}

// =============================================================================
// K2: IoU bitmask, upper-triangular blocks, divide-free fast path with exact
//     fallback near the decision boundary. grid (136, BS), 64 threads.
// =============================================================================
__global__ __launch_bounds__(64) void nms_mask_kernel()
{
    const int b = blockIdx.y;
    int p = blockIdx.x;
    int rb = 0, rem = NWORDS;
    while (p >= rem) { p -= rem; ++rb; --rem; }
    const int cb = rb + p;
    const int i  = rb * 64 + threadIdx.x;

    __shared__ float4 cbox[64];
    __shared__ float  carea[64];
    const int cbase = cb * 64;
    const int ncol  = min(64, KPRE - cbase);
    if (threadIdx.x < ncol) {
        float4 bx = g_boxes[b][cbase + threadIdx.x];
        cbox[threadIdx.x]  = bx;
        carea[threadIdx.x] = (bx.z - bx.x) * (bx.w - bx.y);
    }
    __syncthreads();
    if (i >= KPRE) return;

    u64 bits = 0ull;
    float4 bi = g_boxes[b][i];
    float  ai = (bi.z - bi.x) * (bi.w - bi.y);
    const int j0 = (i >= cbase) ? (i - cbase + 1) : 0;
    for (int j = j0; j < ncol; ++j) {
        float4 bj = cbox[j];
        float lx = fmaxf(bi.x, bj.x);
        float ly = fmaxf(bi.y, bj.y);
        float rx = fminf(bi.z, bj.z);
        float ry = fminf(bi.w, bj.w);
        float w  = fmaxf(rx - lx, 0.0f);
        float h  = fmaxf(ry - ly, 0.0f);
        float inter = w * h;
        float u = ai + carea[j] - inter + 1e-12f;
        float d = inter - NMS_THR * u;
        bool sup = d > 0.0f;
        if (fabsf(d) <= 1e-4f * u)
            sup = (inter / u) > NMS_THR;
        if (sup) bits |= (1ull << j);
    }
    g_mask[b][i][cb] = bits;
}

// =============================================================================
// K3: single-thread greedy scan with single-word removal mask (measured best).
// Triangular preload.
// =============================================================================
extern __shared__ u64 s_mask[];   // KPRE*NWORDS u64 = 128 KB (upper-tri valid)

__global__ __launch_bounds__(1024) void nms_scan_out_kernel(float* __restrict__ out)
{
    const int b   = blockIdx.x;
    const int tid = threadIdx.x;

    __shared__ int s_list[KPOST];
    __shared__ int s_kept;

    const ulonglong2* gm2 = (const ulonglong2*)&g_mask[b][0][0];
    ulonglong2* sm2 = (ulonglong2*)s_mask;
    for (int idx = tid; idx < KPRE * (NWORDS / 2); idx += 1024) {
        int i = idx >> 3;
        int p = idx & 7;
        if (2 * p + 1 >= (i >> 6)) sm2[idx] = gm2[idx];
    }
    __syncthreads();

    if (tid == 0) {
        int kept = 0;
        #pragma unroll 1
        for (int w = 0; w < NWORDS; ++w) {
            if (kept >= KPOST) break;
            const u64 valid = (w == NWORDS - 1)
                ? ((1ull << (KPRE - 64 * (NWORDS - 1))) - 1ull) : ~0ull;

            u64 a0 = 0ull, a1 = 0ull, a2 = 0ull, a3 = 0ull;
            int k = 0;
            for (; k + 4 <= kept; k += 4) {
                a0 |= s_mask[s_list[k + 0] * NWORDS + w];
                a1 |= s_mask[s_list[k + 1] * NWORDS + w];
                a2 |= s_mask[s_list[k + 2] * NWORDS + w];
                a3 |= s_mask[s_list[k + 3] * NWORDS + w];
            }
            for (; k < kept; ++k)
                a0 |= s_mask[s_list[k] * NWORDS + w];
            u64 avail = ~((a0 | a1) | (a2 | a3)) & valid;

            while (avail) {
                int bit = __ffsll((long long)avail) - 1;
                int i = w * 64 + bit;
                s_list[kept++] = i;
                if (kept == KPOST) break;
                u64 rw = s_mask[i * NWORDS + w];
                u64 high = (bit == 63) ? 0ull : (~0ull << (bit + 1));
                avail = avail & ~rw & high;
            }
        }
        s_kept = kept;
    }
    __syncthreads();

    const int kept = s_kept;
    float* ob = out + (size_t)b * KPOST * 5;
    for (int r = tid; r < KPOST; r += 1024) {
        if (r < kept) {
            int i = s_list[r];
            float4 bx = g_boxes[b][i];
            float  sc = g_scores[b][i];
            ob[r * 5 + 0] = bx.x;
            ob[r * 5 + 1] = bx.y;
            ob[r * 5 + 2] = bx.z;
            ob[r * 5 + 3] = bx.w;
            ob[r * 5 + 4] = sc;
        } else {
            ob[r * 5 + 0] = 0.0f;
            ob[r * 5 + 1] = 0.0f;
            ob[r * 5 + 2] = 0.0f;
            ob[r * 5 + 3] = 0.0f;
            ob[r * 5 + 4] = 0.0f;
        }
    }
}

// =============================================================================
extern "C" void kernel_launch(void* const* d_in, const int* in_sizes, int n_in,
                              void* d_out, int out_size)
{
    const float* logits  = (const float*)d_in[0];
    const float* deltas  = (const float*)d_in[1];
    const float* anchors = (const float*)d_in[2];
    const int*   p_ih    = (const int*)d_in[3];
    const int*   p_iw    = (const int*)d_in[4];

    cudaFuncSetAttribute(select_fused_kernel,
                         cudaFuncAttributeMaxDynamicSharedMemorySize,
                         CANDCAP * (int)sizeof(u64));     // 32 KB
    cudaFuncSetAttribute(nms_scan_out_kernel,
                         cudaFuncAttributeMaxDynamicSharedMemorySize,
                         KPRE * NWORDS * (int)sizeof(u64));

    select_fused_kernel<<<dim3(NQ, BS), 1024, CANDCAP * sizeof(u64)>>>(
        logits, deltas, anchors, p_ih, p_iw);
    nms_mask_kernel<<<dim3(NWORDS * (NWORDS + 1) / 2, BS), 64>>>();
    nms_scan_out_kernel<<<BS, 1024, KPRE * NWORDS * sizeof(u64)>>>((float*)d_out);
}

// round 17
// speedup vs baseline: 1.1208x; 1.1208x over previous
#include <cuda_runtime.h>
#include <cstdint>

#define BS 32
#define NANCH 90000
#define NVEC (NANCH / 4)       // 22500 float4 per batch
#define NQ 4                   // slices per batch (grid 128 <= 148 SMs: ONE wave)
#define QVEC (NVEC / NQ)       // 5625
#define KPRE 1000
#define KPOST 300
#define NWORDS 16              // 16*64 = 1024 >= 1000
#define NTRI (NWORDS * (NWORDS + 1) / 2)   // 136 triangular tiles
#define NMS_THR 0.7f

#define HBITS 12
#define NBINS (1 << HBITS)     // 4096 (fallback path only)
#define HSHIFT (32 - HBITS)
#define BPT (NBINS / 1024)
#define QCAP 4096
#define CANDCAP 4096
// flip_f(2.1f) = 0x40066666 | 0x80000000. P(logit>2.1)=0.0179 -> ~1607/batch,
// 15-sigma above KPRE and 11-sigma below 2048 (sort stays at S=2048).
// Exactness guarded: >=KPRE gathered with no overflow => top-1000 subset of
// gathered (full-key ordering). Otherwise exact histogram fallback.
#define GUESS_KEY 0xC0066666u

typedef unsigned long long u64;

// ---------------- scratch (static device globals; no allocation) ----------------
__device__ unsigned g_qcnt[BS][NQ];                    // RAW counts (overflow check)
__device__ u64      g_qcand[BS][NQ][QCAP];
__device__ unsigned g_sync[BS];                        // election counters
__device__ unsigned g_ready[BS];                       // boxes-decoded flags
__device__ unsigned g_mdone[BS];                       // mask-done counters
__device__ float4   g_boxes[BS][KPRE];
__device__ float    g_scores[BS][KPRE];
__device__ __align__(128) u64 g_mask[BS][KPRE][NWORDS]; // lower-tri never written/read

// float -> order-preserving uint (ascending)
__device__ __forceinline__ unsigned flip_f(float f) {
    unsigned u = __float_as_uint(f);
    return (u & 0x80000000u) ? ~u : (u | 0x80000000u);
}
__device__ __forceinline__ float unflip_f(unsigned k) {
    unsigned u = (k & 0x80000000u) ? (k ^ 0x80000000u) : ~k;
    return __uint_as_float(u);
}
__device__ __forceinline__ float read_dim(const int* p) {
    int v = *p;
    if (v > 0 && v < (1 << 24)) return (float)v;
    return __int_as_float(v);
}

// CTA suffix-threshold via warp shfl (FALLBACK PATH ONLY).
__device__ __forceinline__ void find_threshold(
    const unsigned* hist, unsigned* s_wsum, unsigned* s_wafter, unsigned* s_t,
    int tid)
{
    const int lane = tid & 31;
    const int wrp  = tid >> 5;
    const int base = tid * BPT;
    unsigned s = 0;
    #pragma unroll
    for (int k = 0; k < BPT; ++k) s += hist[base + k];

    unsigned val = s;
    #pragma unroll
    for (int off = 1; off < 32; off <<= 1) {
        unsigned v = __shfl_down_sync(0xFFFFFFFFu, val, off);
        if (lane + off < 32) val += v;
    }
    if (lane == 0) s_wsum[wrp] = val;
    __syncthreads();

    if (wrp == 0) {
        unsigned t0 = s_wsum[lane];
        unsigned v0 = t0;
        #pragma unroll
        for (int off = 1; off < 32; off <<= 1) {
            unsigned v = __shfl_down_sync(0xFFFFFFFFu, v0, off);
            if (lane + off < 32) v0 += v;
        }
        s_wafter[lane] = v0 - t0;
    }
    __syncthreads();

    unsigned mine  = val + s_wafter[wrp];
    unsigned above = mine - s;
    if (mine >= KPRE && above < KPRE) {
        unsigned acc = above;
        int t = base;
        #pragma unroll
        for (int k = BPT - 1; k >= 0; --k) {
            acc += hist[base + k];
            if (acc >= KPRE) { t = base + k; break; }
        }
        *s_t = (unsigned)t;
    }
}

// =============================================================================
// K1: slice gather -> election -> elected: verify/concat (or exact fallback)
// -> sort -> decode -> raise flag; then ALL 4 CTAs of the batch compute the
// IoU mask (34 triangular tiles each, 16 groups of 64 threads).
// All 128 CTAs co-resident (one wave) => spin-wait is deadlock-free.
// =============================================================================
extern __shared__ unsigned s_dynA[];   // 32 KB, phase-aliased

__global__ __launch_bounds__(1024, 2) void select_mask_kernel(
    const float* __restrict__ logits,
    const float* __restrict__ deltas,
    const float* __restrict__ anchors,
    const int* __restrict__ p_ih,
    const int* __restrict__ p_iw)
{
    const int b   = blockIdx.y;
    const int q   = blockIdx.x;
    const int tid = threadIdx.x;

    unsigned* hist = s_dynA;                 // fallback only
    u64*      cand = (u64*)s_dynA;
    __shared__ unsigned s_wsum[32];
    __shared__ unsigned s_wafter[32];
    __shared__ unsigned s_t;
    __shared__ unsigned s_cnt;
    __shared__ int s_last;

    const float4* lg4 = (const float4*)(logits + (size_t)b * NANCH);
    const int v0 = q * QVEC;
    const int v1 = v0 + QVEC;

    if (tid == 0) s_cnt = 0u;
    __syncthreads();

    // ---- single sweep: speculative gather (full-key threshold) ----
    for (int i = v0 + tid; i < v1; i += 1024) {
        float4 v = lg4[i];
        unsigned k0 = flip_f(v.x);
        unsigned k1 = flip_f(v.y);
        unsigned k2 = flip_f(v.z);
        unsigned k3 = flip_f(v.w);
        const int i0 = 4 * i;
        if (k0 >= GUESS_KEY) {
            unsigned p = atomicAdd(&s_cnt, 1u);
            if (p < QCAP) g_qcand[b][q][p] = ((u64)k0 << 32) | (unsigned)(~(unsigned)(i0));
        }
        if (k1 >= GUESS_KEY) {
            unsigned p = atomicAdd(&s_cnt, 1u);
            if (p < QCAP) g_qcand[b][q][p] = ((u64)k1 << 32) | (unsigned)(~(unsigned)(i0 + 1));
        }
        if (k2 >= GUESS_KEY) {
            unsigned p = atomicAdd(&s_cnt, 1u);
            if (p < QCAP) g_qcand[b][q][p] = ((u64)k2 << 32) | (unsigned)(~(unsigned)(i0 + 2));
        }
        if (k3 >= GUESS_KEY) {
            unsigned p = atomicAdd(&s_cnt, 1u);
            if (p < QCAP) g_qcand[b][q][p] = ((u64)k3 << 32) | (unsigned)(~(unsigned)(i0 + 3));
        }
    }
    __syncthreads();

    // ---- publish raw count, elect last CTA of this batch ----
    if (tid == 0) {
        g_qcnt[b][q] = s_cnt;
        __threadfence();
        unsigned old = atomicAdd(&g_sync[b], 1u);
        s_last = (old == NQ - 1);
        if (s_last) g_sync[b] = 0u;
    }
    __syncthreads();

    if (s_last) {
        // =================== global select (elected CTA only) ===================
        __threadfence();

        const unsigned r0 = g_qcnt[b][0];
        const unsigned r1 = g_qcnt[b][1];
        const unsigned r2 = g_qcnt[b][2];
        const unsigned r3 = g_qcnt[b][3];
        const unsigned total = r0 + r1 + r2 + r3;
        const bool spec_ok = (r0 <= QCAP) && (r1 <= QCAP) && (r2 <= QCAP) && (r3 <= QCAP)
                          && (total >= KPRE) && (total <= CANDCAP);
        int n;
        if (spec_ok) {
            const unsigned off1 = r0, off2 = r0 + r1, off3 = r0 + r1 + r2;
            for (unsigned i = tid; i < r0; i += 1024) cand[i]        = g_qcand[b][0][i];
            for (unsigned i = tid; i < r1; i += 1024) cand[off1 + i] = g_qcand[b][1][i];
            for (unsigned i = tid; i < r2; i += 1024) cand[off2 + i] = g_qcand[b][2][i];
            for (unsigned i = tid; i < r3; i += 1024) cand[off3 + i] = g_qcand[b][3][i];
            n = (int)total;
        } else {
            // ---- exact fallback: hist -> threshold -> gather (cold path) ----
            for (int i = tid; i < NBINS; i += 1024) hist[i] = 0u;
            if (tid == 0) s_cnt = 0u;
            __syncthreads();
            for (int i = tid; i < NVEC; i += 1024) {
                float4 v = lg4[i];
                atomicAdd(&hist[flip_f(v.x) >> HSHIFT], 1u);
                atomicAdd(&hist[flip_f(v.y) >> HSHIFT], 1u);
                atomicAdd(&hist[flip_f(v.z) >> HSHIFT], 1u);
                atomicAdd(&hist[flip_f(v.w) >> HSHIFT], 1u);
            }
            __syncthreads();
            find_threshold(hist, s_wsum, s_wafter, &s_t, tid);
            __syncthreads();
            const unsigned t = s_t;
            __syncthreads();
            for (int i = tid; i < NVEC; i += 1024) {
                float4 v = lg4[i];
                unsigned kk[4] = { flip_f(v.x), flip_f(v.y), flip_f(v.z), flip_f(v.w) };
                const int i0 = 4 * i;
                #pragma unroll
                for (int c = 0; c < 4; ++c) {
                    if ((kk[c] >> HSHIFT) >= t) {
                        unsigned p = atomicAdd(&s_cnt, 1u);
                        if (p < CANDCAP)
                            cand[p] = ((u64)kk[c] << 32) | (unsigned)(~(unsigned)(i0 + c));
                    }
                }
            }
            __syncthreads();
            n = min((int)s_cnt, CANDCAP);
        }
        __syncthreads();

        const int S = (n <= 2048) ? 2048 : CANDCAP;
        for (int i = n + tid; i < S; i += 1024) cand[i] = 0ull;

        // ---- bitonic sort desc; full barrier only around cross-warp strides ----
        int prev_big = 1;
        for (int size = 2; size <= S; size <<= 1) {
            for (int stride = size >> 1; stride > 0; stride >>= 1) {
                const int big = (stride >= 32);
                if (big || prev_big) __syncthreads(); else __syncwarp();
                for (int k = tid; k < (S >> 1); k += 1024) {
                    int i = 2 * k - (k & (stride - 1));
                    int j = i + stride;
                    u64 a = cand[i];
                    u64 c = cand[j];
                    bool desc = ((i & size) == 0);
                    if ((a < c) == desc) { cand[i] = c; cand[j] = a; }
                }
                prev_big = big;
            }
        }
        __syncthreads();

        // ---- decode + clip top-1000 ----
        const float fw = read_dim(p_iw);
        const float fh = read_dim(p_ih);
        if (tid < KPRE) {
            u64 comp = cand[tid];
            unsigned idx = ~(unsigned)(comp & 0xFFFFFFFFull);
            unsigned key = (unsigned)(comp >> 32);
            float logit = unflip_f(key);
            float score = 1.0f / (1.0f + expf(-logit));

            float4 d = ((const float4*)deltas)[(size_t)b * NANCH + idx];
            float4 a = ((const float4*)anchors)[idx];
            float aw  = a.z - a.x;
            float ah  = a.w - a.y;
            float acx = a.x + 0.5f * aw;
            float acy = a.y + 0.5f * ah;
            float cx = d.x * aw + acx;
            float cy = d.y * ah + acy;
            float w  = expf(d.z) * aw;
            float h  = expf(d.w) * ah;
            float x1 = fminf(fmaxf(cx - 0.5f * w, 0.0f), fw);
            float y1 = fminf(fmaxf(cy - 0.5f * h, 0.0f), fh);
            float x2 = fminf(fmaxf(cx + 0.5f * w, 0.0f), fw);
            float y2 = fminf(fmaxf(cy + 0.5f * h, 0.0f), fh);
            g_boxes[b][tid]  = make_float4(x1, y1, x2, y2);
            g_scores[b][tid] = score;
        }
        __threadfence();     // all decode writes visible chip-wide
        __syncthreads();
        if (tid == 0) atomicExch(&g_ready[b], 1u);   // raise flag
        __syncthreads();     // smem (cand) dead before mask-phase reuse
    } else {
        // ---- wait for this batch's boxes ----
        if (tid == 0) {
            while (atomicAdd(&g_ready[b], 0u) == 0u) { }
            __threadfence();
        }
        __syncthreads();
    }

    // =================== mask phase (all NQ CTAs of the batch) ===============
    // CTA q handles triangular tiles p with p % NQ == q (34 tiles), split
    // across 16 groups of 64 threads: p = q + 4*g + 64*k, k = 0..2.
    float4* cbox  = (float4*)s_dynA;                   // [16][64] = 16 KB
    float*  carea = (float*)s_dynA + 16 * 64 * 4;      // [16][64] =  4 KB
    const int g = tid >> 6;
    const int r = tid & 63;

    #pragma unroll 1
    for (int k = 0; k < 3; ++k) {
        const int p = q + 4 * g + 64 * k;
        const bool active = (p < NTRI);
        int rb = 0, cb = 0;
        if (active) {
            int pp = p, rem = NWORDS;
            while (pp >= rem) { pp -= rem; ++rb; --rem; }
            cb = rb + pp;
        }
        __syncthreads();              // protect slab reuse across k
        int cbase = cb * 64;
        int ncol  = min(64, KPRE - cbase);
        if (active && r < ncol) {
            float4 bx = g_boxes[b][cbase + r];
            cbox[g * 64 + r]  = bx;
            carea[g * 64 + r] = (bx.z - bx.x) * (bx.w - bx.y);
        }
        __syncthreads();
        if (active) {
            const int i = rb * 64 + r;
            if (i < KPRE) {
                u64 bits = 0ull;
                float4 bi = g_boxes[b][i];
                float  ai = (bi.z - bi.x) * (bi.w - bi.y);
                const int j0 = (i >= cbase) ? (i - cbase + 1) : 0;
                for (int j = j0; j < ncol; ++j) {
                    float4 bj = cbox[g * 64 + j];
                    float lx = fmaxf(bi.x, bj.x);
                    float ly = fmaxf(bi.y, bj.y);
                    float rx = fminf(bi.z, bj.z);
                    float ry = fminf(bi.w, bj.w);
                    float w  = fmaxf(rx - lx, 0.0f);
                    float h  = fmaxf(ry - ly, 0.0f);
                    float inter = w * h;
                    float u = ai + carea[g * 64 + j] - inter + 1e-12f;
                    float d = inter - NMS_THR * u;
                    bool sup = d > 0.0f;
                    if (fabsf(d) <= 1e-4f * u)
                        sup = (inter / u) > NMS_THR;
                    if (sup) bits |= (1ull << j);
                }
                g_mask[b][i][cb] = bits;
            }
        }
    }

    // ---- reset handshake for next graph replay ----
    __syncthreads();
    if (tid == 0) {
        unsigned old = atomicAdd(&g_mdone[b], 1u);
        if (old == NQ - 1) { g_mdone[b] = 0u; g_ready[b] = 0u; }
    }
}

// =============================================================================
// K3: single-thread greedy scan with single-word removal mask (measured best).
// Triangular preload.
// =============================================================================
extern __shared__ u64 s_mask[];   // KPRE*NWORDS u64 = 128 KB (upper-tri valid)

__global__ __launch_bounds__(1024) void nms_scan_out_kernel(float* __restrict__ out)
{
    const int b   = blockIdx.x;
    const int tid = threadIdx.x;

    __shared__ int s_list[KPOST];
    __shared__ int s_kept;

    const ulonglong2* gm2 = (const ulonglong2*)&g_mask[b][0][0];
    ulonglong2* sm2 = (ulonglong2*)s_mask;
    for (int idx = tid; idx < KPRE * (NWORDS / 2); idx += 1024) {
        int i = idx >> 3;
        int p = idx & 7;
        if (2 * p + 1 >= (i >> 6)) sm2[idx] = gm2[idx];
    }
    __syncthreads();

    if (tid == 0) {
        int kept = 0;
        #pragma unroll 1
        for (int w = 0; w < NWORDS; ++w) {
            if (kept >= KPOST) break;
            const u64 valid = (w == NWORDS - 1)
                ? ((1ull << (KPRE - 64 * (NWORDS - 1))) - 1ull) : ~0ull;

            u64 a0 = 0ull, a1 = 0ull, a2 = 0ull, a3 = 0ull;
            int k = 0;
            for (; k + 4 <= kept; k += 4) {
                a0 |= s_mask[s_list[k + 0] * NWORDS + w];
                a1 |= s_mask[s_list[k + 1] * NWORDS + w];
                a2 |= s_mask[s_list[k + 2] * NWORDS + w];
                a3 |= s_mask[s_list[k + 3] * NWORDS + w];
            }
            for (; k < kept; ++k)
                a0 |= s_mask[s_list[k] * NWORDS + w];
            u64 avail = ~((a0 | a1) | (a2 | a3)) & valid;

            while (avail) {
                int bit = __ffsll((long long)avail) - 1;
                int i = w * 64 + bit;
                s_list[kept++] = i;
                if (kept == KPOST) break;
                u64 rw = s_mask[i * NWORDS + w];
                u64 high = (bit == 63) ? 0ull : (~0ull << (bit + 1));
                avail = avail & ~rw & high;
            }
        }
        s_kept = kept;
    }
    __syncthreads();

    const int kept = s_kept;
    float* ob = out + (size_t)b * KPOST * 5;
    for (int r = tid; r < KPOST; r += 1024) {
        if (r < kept) {
            int i = s_list[r];
            float4 bx = g_boxes[b][i];
            float  sc = g_scores[b][i];
            ob[r * 5 + 0] = bx.x;
            ob[r * 5 + 1] = bx.y;
            ob[r * 5 + 2] = bx.z;
            ob[r * 5 + 3] = bx.w;
            ob[r * 5 + 4] = sc;
        } else {
            ob[r * 5 + 0] = 0.0f;
            ob[r * 5 + 1] = 0.0f;
            ob[r * 5 + 2] = 0.0f;
            ob[r * 5 + 3] = 0.0f;
            ob[r * 5 + 4] = 0.0f;
        }
    }
}

// =============================================================================
extern "C" void kernel_launch(void* const* d_in, const int* in_sizes, int n_in,
                              void* d_out, int out_size)
{
    const float* logits  = (const float*)d_in[0];
    const float* deltas  = (const float*)d_in[1];
    const float* anchors = (const float*)d_in[2];
    const int*   p_ih    = (const int*)d_in[3];
    const int*   p_iw    = (const int*)d_in[4];

    cudaFuncSetAttribute(select_mask_kernel,
                         cudaFuncAttributeMaxDynamicSharedMemorySize,
                         CANDCAP * (int)sizeof(u64));     // 32 KB
    cudaFuncSetAttribute(nms_scan_out_kernel,
                         cudaFuncAttributeMaxDynamicSharedMemorySize,
                         KPRE * NWORDS * (int)sizeof(u64));

    select_mask_kernel<<<dim3(NQ, BS), 1024, CANDCAP * sizeof(u64)>>>(
        logits, deltas, anchors, p_ih, p_iw);
    nms_scan_out_kernel<<<BS, 1024, KPRE * NWORDS * sizeof(u64)>>>((float*)d_out);
}